// round 4
// baseline (speedup 1.0000x reference)
#include <cuda_runtime.h>
#include <cstdint>

// ---------------------------------------------------------------------------
// EncoderLayer: x -> MHA(flash) -> add&LN -> FF(relu) -> add&LN
// B=4, S=2048, D=1024, H=16, hd=64, FF=4096, fp32 in/out.
// Round 4: occupancy push. Flash P-fragments via shuffles (no P smem),
// 2 CTAs/SM for both flash and GEMM; GEMM 2-stage cp.async.
// ---------------------------------------------------------------------------

namespace cfg {
constexpr int D_MODEL = 1024;
constexpr int NHEADS  = 16;
constexpr int HDIM    = 64;
constexpr int DFF     = 4096;
constexpr int BATCH   = 4;
constexpr int SEQ     = 2048;
constexpr int NTOK    = BATCH * SEQ;   // 8192
}

// ------------------------------ scratch ------------------------------------
__device__ float g_q   [(size_t)cfg::NTOK * cfg::D_MODEL];
__device__ float g_k   [(size_t)cfg::NTOK * cfg::D_MODEL];
__device__ float g_v   [(size_t)cfg::NTOK * cfg::D_MODEL];
__device__ float g_attn[(size_t)cfg::NTOK * cfg::D_MODEL];
__device__ float g_h   [(size_t)cfg::NTOK * cfg::D_MODEL];
__device__ float g_ff  [(size_t)cfg::NTOK * cfg::DFF];

// ------------------------------ helpers ------------------------------------
__device__ __forceinline__ void cp16(void* s, const void* g) {
    uint32_t sa = (uint32_t)__cvta_generic_to_shared(s);
    asm volatile("cp.async.cg.shared.global [%0], [%1], 16;\n" :: "r"(sa), "l"(g));
}
__device__ __forceinline__ void cp_commit() {
    asm volatile("cp.async.commit_group;\n");
}
template <int N>
__device__ __forceinline__ void cp_wait() {
    asm volatile("cp.async.wait_group %0;\n" :: "n"(N));
}

// mma with raw fp32 operands interpreted as tf32 (RZ truncation in HW).
__device__ __forceinline__ void mma_m16n8k8(float* c, const uint32_t* a, const uint32_t* b) {
    asm volatile(
        "mma.sync.aligned.m16n8k8.row.col.f32.tf32.tf32.f32 "
        "{%0,%1,%2,%3}, {%4,%5,%6,%7}, {%8,%9}, {%0,%1,%2,%3};\n"
        : "+f"(c[0]), "+f"(c[1]), "+f"(c[2]), "+f"(c[3])
        : "r"(a[0]), "r"(a[1]), "r"(a[2]), "r"(a[3]),
          "r"(b[0]), "r"(b[1]));
}

// ------------------------------ GEMM (cp.async, 2-stage) --------------------
// C[M,N] = alpha * A[M,K] @ B[K,N] + bias, optional ReLU. Row-major.
namespace gg {
constexpr int BM = 128, BN = 128, BK = 32, STG = 2;
constexpr int LDA = 36;    // 4*grp+tg = lane -> conflict-free A frag reads
constexpr int LDB = 136;   // 8*tg+grp -> conflict-free B frag reads
constexpr int STAGE_FLOATS = BM * LDA + BK * LDB;   // 8960
constexpr int SMEM_BYTES = STG * STAGE_FLOATS * 4;  // 71680
}

template <bool RELU>
__global__ void __launch_bounds__(256, 2) gemm_cp(
    const float* __restrict__ A, const float* __restrict__ B,
    const float* __restrict__ bias, float* __restrict__ C,
    int N, int K, float alpha)
{
    using namespace gg;
    extern __shared__ float sm[];

    const int tid  = threadIdx.x;
    const int lane = tid & 31;
    const int warp = tid >> 5;
    const int wm   = warp & 1;          // 2 warps along M (64 each)
    const int wn   = warp >> 1;         // 4 warps along N (32 each)
    const int grp  = lane >> 2;
    const int tg   = lane & 3;
    const int bm   = blockIdx.y * BM;
    const int bn   = blockIdx.x * BN;

    const int at_row = tid >> 3;            // 0..31, +i*32
    const int at_col = (tid & 7) << 2;      // 0..28
    const int bt_row = tid >> 5;            // 0..7, +i*8
    const int bt_col = (tid & 31) << 2;     // 0..124

    auto issue = [&](int kt, int stg) {
        float* sA = sm + stg * STAGE_FLOATS;
        float* sB = sA + BM * LDA;
        const int k0 = kt * BK;
        #pragma unroll
        for (int i = 0; i < 4; i++) {
            int r = at_row + i * 32;
            cp16(&sA[r * LDA + at_col],
                 &A[(size_t)(bm + r) * K + k0 + at_col]);
        }
        #pragma unroll
        for (int i = 0; i < 4; i++) {
            int r = bt_row + i * 8;
            cp16(&sB[r * LDB + bt_col],
                 &B[(size_t)(k0 + r) * N + bn + bt_col]);
        }
    };

    float acc[4][4][4];
    #pragma unroll
    for (int mi = 0; mi < 4; mi++)
        #pragma unroll
        for (int ni = 0; ni < 4; ni++)
            #pragma unroll
            for (int j = 0; j < 4; j++) acc[mi][ni][j] = 0.f;

    const int ntiles = K / BK;
    issue(0, 0); cp_commit();
    issue(1, 1); cp_commit();

    for (int kt = 0; kt < ntiles; kt++) {
        cp_wait<1>();
        __syncthreads();

        const float* sA = sm + (kt & 1) * STAGE_FLOATS;
        const float* sB = sA + BM * LDA;

        #pragma unroll
        for (int kk = 0; kk < BK; kk += 8) {
            uint32_t af[4][4];
            uint32_t bf[4][2];
            #pragma unroll
            for (int mi = 0; mi < 4; mi++) {
                const int r = wm * 64 + mi * 16;
                af[mi][0] = __float_as_uint(sA[(r + grp    ) * LDA + kk + tg    ]);
                af[mi][1] = __float_as_uint(sA[(r + grp + 8) * LDA + kk + tg    ]);
                af[mi][2] = __float_as_uint(sA[(r + grp    ) * LDA + kk + tg + 4]);
                af[mi][3] = __float_as_uint(sA[(r + grp + 8) * LDA + kk + tg + 4]);
            }
            #pragma unroll
            for (int ni = 0; ni < 4; ni++) {
                const int c = wn * 32 + ni * 8 + grp;
                bf[ni][0] = __float_as_uint(sB[(kk + tg    ) * LDB + c]);
                bf[ni][1] = __float_as_uint(sB[(kk + tg + 4) * LDB + c]);
            }
            #pragma unroll
            for (int mi = 0; mi < 4; mi++)
                #pragma unroll
                for (int ni = 0; ni < 4; ni++)
                    mma_m16n8k8(acc[mi][ni], af[mi], bf[ni]);
        }

        __syncthreads();
        if (kt + 2 < ntiles) issue(kt + 2, kt & 1);
        cp_commit();
    }

    #pragma unroll
    for (int mi = 0; mi < 4; mi++) {
        const int r0 = bm + wm * 64 + mi * 16 + grp;
        #pragma unroll
        for (int ni = 0; ni < 4; ni++) {
            const int c0 = bn + wn * 32 + ni * 8 + tg * 2;
            float bv0 = 0.f, bv1 = 0.f;
            if (bias) { bv0 = __ldg(&bias[c0]); bv1 = __ldg(&bias[c0 + 1]); }
            float v0 = acc[mi][ni][0] * alpha + bv0;
            float v1 = acc[mi][ni][1] * alpha + bv1;
            float v2 = acc[mi][ni][2] * alpha + bv0;
            float v3 = acc[mi][ni][3] * alpha + bv1;
            if (RELU) {
                v0 = fmaxf(v0, 0.f); v1 = fmaxf(v1, 0.f);
                v2 = fmaxf(v2, 0.f); v3 = fmaxf(v3, 0.f);
            }
            *reinterpret_cast<float2*>(&C[(size_t)r0 * N + c0]) =
                make_float2(v0, v1);
            *reinterpret_cast<float2*>(&C[(size_t)(r0 + 8) * N + c0]) =
                make_float2(v2, v3);
        }
    }
}

// --------------------------- flash attention --------------------------------
// One CTA = 128 Q rows of one (b,h). 8 warps x 16 rows. KV tiles of 64,
// double-buffered via cp.async. P fragments built by intra-quad shuffles
// (no P smem). 2 CTAs/SM.
namespace fa {
constexpr int BQ  = 128;
constexpr int BKV = 64;
constexpr int LDK = 68;
constexpr int LDV = 72;
constexpr int SMEM_FLOATS = 2 * BKV * LDK + 2 * BKV * LDV;  // 17920
constexpr int SMEM_BYTES  = SMEM_FLOATS * 4;                // 71680
}

__global__ void __launch_bounds__(256, 2) flash_attn(
    const float* __restrict__ Q, const float* __restrict__ K,
    const float* __restrict__ V, float* __restrict__ O)
{
    using namespace fa;
    extern __shared__ float sm[];
    float* Ks = sm;
    float* Vs = sm + 2 * BKV * LDK;

    const int tid  = threadIdx.x;
    const int lane = tid & 31;
    const int warp = tid >> 5;
    const int grp  = lane >> 2;
    const int tg   = lane & 3;
    const int bh   = blockIdx.y;
    const int b    = bh >> 4;
    const int h    = bh & 15;
    const long long base = (long long)b * ((long long)cfg::SEQ * cfg::D_MODEL)
                         + (long long)h * cfg::HDIM;
    const float* Qp = Q + base;
    const float* Kp = K + base;
    const float* Vp = V + base;
    const int bm   = blockIdx.x * BQ;
    const int wrow = warp * 16;

    const int kr = tid >> 4;           // 0..15
    const int kc = (tid & 15) << 2;    // 0..60

    // ---- stage Q tile (x 1/8) through the K region (not yet loaded) ----
    {
        constexpr int LDQ = 68;
        #pragma unroll
        for (int i = 0; i < 8; i++) {
            int row = kr + i * 16;
            float4 qv = *reinterpret_cast<const float4*>(
                Qp + (long long)(bm + row) * cfg::D_MODEL + kc);
            float* d = &sm[row * LDQ + kc];
            d[0] = qv.x * 0.125f; d[1] = qv.y * 0.125f;
            d[2] = qv.z * 0.125f; d[3] = qv.w * 0.125f;
        }
        __syncthreads();
        // fall through: qf loaded below, then sync before cp.async overwrites
    }
    uint32_t qf[8][4];
    #pragma unroll
    for (int kk = 0; kk < 8; kk++) {
        constexpr int LDQ = 68;
        qf[kk][0] = __float_as_uint(sm[(wrow + grp    ) * LDQ + kk * 8 + tg    ]);
        qf[kk][1] = __float_as_uint(sm[(wrow + grp + 8) * LDQ + kk * 8 + tg    ]);
        qf[kk][2] = __float_as_uint(sm[(wrow + grp    ) * LDQ + kk * 8 + tg + 4]);
        qf[kk][3] = __float_as_uint(sm[(wrow + grp + 8) * LDQ + kk * 8 + tg + 4]);
    }
    __syncthreads();

    auto issue_kv = [&](int t, int bf) {
        #pragma unroll
        for (int i = 0; i < 4; i++) {
            int row = kr + i * 16;
            long long grow = (long long)(t * BKV + row) * cfg::D_MODEL + kc;
            cp16(&Ks[(bf * BKV + row) * LDK + kc], Kp + grow);
            cp16(&Vs[(bf * BKV + row) * LDV + kc], Vp + grow);
        }
    };

    issue_kv(0, 0); cp_commit();

    float oacc[8][4];
    #pragma unroll
    for (int ni = 0; ni < 8; ni++)
        #pragma unroll
        for (int j = 0; j < 4; j++) oacc[ni][j] = 0.f;
    float m0 = -3.402823466e38f, m1 = -3.402823466e38f;
    float l0 = 0.f, l1 = 0.f;

    // shuffle sources for C-frag -> A-frag conversion
    const int src  = grp * 4 + (tg >> 1);
    const int src2 = src + 2;
    const bool odd = (tg & 1);

    constexpr int NT = cfg::SEQ / BKV;   // 32
    for (int t = 0; t < NT; t++) {
        cp_wait<0>();
        __syncthreads();
        if (t + 1 < NT) issue_kv(t + 1, (t + 1) & 1);
        cp_commit();

        const int buf = t & 1;

        // ---- S = (Q/8) @ K^T ----
        float sacc[8][4];
        #pragma unroll
        for (int ni = 0; ni < 8; ni++)
            #pragma unroll
            for (int j = 0; j < 4; j++) sacc[ni][j] = 0.f;

        const float* Kb = Ks + buf * BKV * LDK;
        #pragma unroll
        for (int kk = 0; kk < 8; kk++) {
            #pragma unroll
            for (int ni = 0; ni < 8; ni++) {
                uint32_t bb[2] = {
                    __float_as_uint(Kb[(ni * 8 + grp) * LDK + kk * 8 + tg    ]),
                    __float_as_uint(Kb[(ni * 8 + grp) * LDK + kk * 8 + tg + 4])};
                mma_m16n8k8(sacc[ni], qf[kk], bb);
            }
        }

        // ---- online softmax (rows grp and grp+8 of this warp) ----
        float mx0 = -3.402823466e38f, mx1 = -3.402823466e38f;
        #pragma unroll
        for (int ni = 0; ni < 8; ni++) {
            mx0 = fmaxf(mx0, fmaxf(sacc[ni][0], sacc[ni][1]));
            mx1 = fmaxf(mx1, fmaxf(sacc[ni][2], sacc[ni][3]));
        }
        mx0 = fmaxf(mx0, __shfl_xor_sync(0xffffffffu, mx0, 1));
        mx0 = fmaxf(mx0, __shfl_xor_sync(0xffffffffu, mx0, 2));
        mx1 = fmaxf(mx1, __shfl_xor_sync(0xffffffffu, mx1, 1));
        mx1 = fmaxf(mx1, __shfl_xor_sync(0xffffffffu, mx1, 2));

        const float mn0 = fmaxf(m0, mx0);
        const float mn1 = fmaxf(m1, mx1);
        const float a0  = __expf(m0 - mn0);
        const float a1  = __expf(m1 - mn1);
        m0 = mn0; m1 = mn1;

        float rs0 = 0.f, rs1 = 0.f;
        #pragma unroll
        for (int ni = 0; ni < 8; ni++) {
            sacc[ni][0] = __expf(sacc[ni][0] - m0);
            sacc[ni][1] = __expf(sacc[ni][1] - m0);
            sacc[ni][2] = __expf(sacc[ni][2] - m1);
            sacc[ni][3] = __expf(sacc[ni][3] - m1);
            rs0 += sacc[ni][0] + sacc[ni][1];
            rs1 += sacc[ni][2] + sacc[ni][3];
        }
        l0 = l0 * a0 + rs0;
        l1 = l1 * a1 + rs1;
        #pragma unroll
        for (int ni = 0; ni < 8; ni++) {
            oacc[ni][0] *= a0; oacc[ni][1] *= a0;
            oacc[ni][2] *= a1; oacc[ni][3] *= a1;
        }

        // ---- O += P @ V  (P A-frags via intra-quad shuffles) ----
        const float* Vb = Vs + buf * BKV * LDV;
        #pragma unroll
        for (int kk = 0; kk < 8; kk++) {
            // C-frag sacc[kk] covers P cols [kk*8, kk*8+8): exactly the
            // k-slice needed for the kk-th A fragment of P@V.
            float s0a = __shfl_sync(0xffffffffu, sacc[kk][0], src);
            float s1a = __shfl_sync(0xffffffffu, sacc[kk][1], src);
            float s2a = __shfl_sync(0xffffffffu, sacc[kk][2], src);
            float s3a = __shfl_sync(0xffffffffu, sacc[kk][3], src);
            float s0b = __shfl_sync(0xffffffffu, sacc[kk][0], src2);
            float s1b = __shfl_sync(0xffffffffu, sacc[kk][1], src2);
            float s2b = __shfl_sync(0xffffffffu, sacc[kk][2], src2);
            float s3b = __shfl_sync(0xffffffffu, sacc[kk][3], src2);
            uint32_t af[4];
            af[0] = __float_as_uint(odd ? s1a : s0a);   // row grp,   k=tg
            af[1] = __float_as_uint(odd ? s3a : s2a);   // row grp+8, k=tg
            af[2] = __float_as_uint(odd ? s1b : s0b);   // row grp,   k=tg+4
            af[3] = __float_as_uint(odd ? s3b : s2b);   // row grp+8, k=tg+4
            #pragma unroll
            for (int ni = 0; ni < 8; ni++) {
                uint32_t bb[2] = {
                    __float_as_uint(Vb[(kk * 8 + tg    ) * LDV + ni * 8 + grp]),
                    __float_as_uint(Vb[(kk * 8 + tg + 4) * LDV + ni * 8 + grp])};
                mma_m16n8k8(oacc[ni], af, bb);
            }
        }
    }

    // ---- epilogue: normalize and store ----
    l0 += __shfl_xor_sync(0xffffffffu, l0, 1);
    l0 += __shfl_xor_sync(0xffffffffu, l0, 2);
    l1 += __shfl_xor_sync(0xffffffffu, l1, 1);
    l1 += __shfl_xor_sync(0xffffffffu, l1, 2);
    const float inv0 = 1.f / l0;
    const float inv1 = 1.f / l1;

    const long long tok0 = (long long)b * cfg::SEQ + bm + wrow + grp;
    #pragma unroll
    for (int ni = 0; ni < 8; ni++) {
        const int c = h * cfg::HDIM + ni * 8 + tg * 2;
        *reinterpret_cast<float2*>(&O[tok0 * cfg::D_MODEL + c]) =
            make_float2(oacc[ni][0] * inv0, oacc[ni][1] * inv0);
        *reinterpret_cast<float2*>(&O[(tok0 + 8) * cfg::D_MODEL + c]) =
            make_float2(oacc[ni][2] * inv1, oacc[ni][3] * inv1);
    }
}

// ------------------------------ add + LayerNorm ----------------------------
__global__ void __launch_bounds__(256) add_ln_kernel(
    const float* __restrict__ a, const float* __restrict__ b,
    const float* __restrict__ gamma, const float* __restrict__ beta,
    float* __restrict__ outp)
{
    const long long row = blockIdx.x;
    const float* pa = a + row * cfg::D_MODEL;
    const float* pb = b + row * cfg::D_MODEL;
    float* po = outp + row * cfg::D_MODEL;
    const int tid = threadIdx.x;

    float v[4];
    float s = 0.f, sq = 0.f;
    #pragma unroll
    for (int i = 0; i < 4; i++) {
        const int c = i * 256 + tid;
        v[i] = pa[c] + pb[c];
        s += v[i];
        sq += v[i] * v[i];
    }

    __shared__ float r1[8], r2[8];
    #pragma unroll
    for (int o = 16; o > 0; o >>= 1) {
        s  += __shfl_xor_sync(0xffffffffu, s, o);
        sq += __shfl_xor_sync(0xffffffffu, sq, o);
    }
    if ((tid & 31) == 0) { r1[tid >> 5] = s; r2[tid >> 5] = sq; }
    __syncthreads();
    s = 0.f; sq = 0.f;
    #pragma unroll
    for (int j = 0; j < 8; j++) { s += r1[j]; sq += r2[j]; }

    const float mu   = s * (1.f / cfg::D_MODEL);
    const float var  = sq * (1.f / cfg::D_MODEL) - mu * mu;
    const float rstd = rsqrtf(var + 1e-5f);

    #pragma unroll
    for (int i = 0; i < 4; i++) {
        const int c = i * 256 + tid;
        po[c] = (v[i] - mu) * rstd * __ldg(&gamma[c]) + __ldg(&beta[c]);
    }
}

// ------------------------------ launch -------------------------------------
extern "C" void kernel_launch(void* const* d_in, const int* in_sizes, int n_in,
                              void* d_out, int out_size)
{
    using namespace cfg;
    const float* x   = (const float*)d_in[0];
    const float* Wq  = (const float*)d_in[1];
    const float* bq  = (const float*)d_in[2];
    const float* Wk  = (const float*)d_in[3];
    const float* bk_ = (const float*)d_in[4];
    const float* Wv  = (const float*)d_in[5];
    const float* bv  = (const float*)d_in[6];
    const float* Wo  = (const float*)d_in[7];
    const float* bo  = (const float*)d_in[8];
    const float* W1  = (const float*)d_in[9];
    const float* b1  = (const float*)d_in[10];
    const float* W2  = (const float*)d_in[11];
    const float* b2  = (const float*)d_in[12];
    const float* g1  = (const float*)d_in[13];
    const float* be1 = (const float*)d_in[14];
    const float* g2  = (const float*)d_in[15];
    const float* be2 = (const float*)d_in[16];
    float* out = (float*)d_out;

    float *q, *k, *v, *attn, *h, *ff;
    cudaGetSymbolAddress((void**)&q,    g_q);
    cudaGetSymbolAddress((void**)&k,    g_k);
    cudaGetSymbolAddress((void**)&v,    g_v);
    cudaGetSymbolAddress((void**)&attn, g_attn);
    cudaGetSymbolAddress((void**)&h,    g_h);
    cudaGetSymbolAddress((void**)&ff,   g_ff);

    static bool attr_done = false;
    if (!attr_done) {
        cudaFuncSetAttribute(flash_attn,
                             cudaFuncAttributeMaxDynamicSharedMemorySize,
                             fa::SMEM_BYTES);
        cudaFuncSetAttribute(gemm_cp<false>,
                             cudaFuncAttributeMaxDynamicSharedMemorySize,
                             gg::SMEM_BYTES);
        cudaFuncSetAttribute(gemm_cp<true>,
                             cudaFuncAttributeMaxDynamicSharedMemorySize,
                             gg::SMEM_BYTES);
        attr_done = true;
    }

    // 1) Q/K/V projections: [8192,1024] @ [1024,1024] + bias
    {
        dim3 grid(D_MODEL / 128, NTOK / 128);
        gemm_cp<false><<<grid, 256, gg::SMEM_BYTES>>>(x, Wq, bq, q, D_MODEL, D_MODEL, 1.f);
        gemm_cp<false><<<grid, 256, gg::SMEM_BYTES>>>(x, Wk, bk_, k, D_MODEL, D_MODEL, 1.f);
        gemm_cp<false><<<grid, 256, gg::SMEM_BYTES>>>(x, Wv, bv, v, D_MODEL, D_MODEL, 1.f);
    }

    // 2-4) fused flash attention -> attn
    {
        dim3 grid(SEQ / fa::BQ, BATCH * NHEADS);
        flash_attn<<<grid, 256, fa::SMEM_BYTES>>>(q, k, v, attn);
    }

    // 5) output projection: attn @ Wo + bo -> reuse q
    {
        dim3 grid(D_MODEL / 128, NTOK / 128);
        gemm_cp<false><<<grid, 256, gg::SMEM_BYTES>>>(attn, Wo, bo, q, D_MODEL, D_MODEL, 1.f);
    }

    // 6) h = LN(x + proj)
    add_ln_kernel<<<NTOK, 256>>>(x, q, g1, be1, h);

    // 7) ff = relu(h @ W1 + b1)
    {
        dim3 grid(DFF / 128, NTOK / 128);
        gemm_cp<true><<<grid, 256, gg::SMEM_BYTES>>>(h, W1, b1, ff, DFF, D_MODEL, 1.f);
    }

    // 8) ff2 = ff @ W2 + b2 -> reuse k
    {
        dim3 grid(D_MODEL / 128, NTOK / 128);
        gemm_cp<false><<<grid, 256, gg::SMEM_BYTES>>>(ff, W2, b2, k, D_MODEL, DFF, 1.f);
    }

    // 9) out = LN(h + ff2)
    add_ln_kernel<<<NTOK, 256>>>(h, k, g2, be2, out);
}

// round 5
// speedup vs baseline: 1.5335x; 1.5335x over previous
#include <cuda_runtime.h>
#include <cstdint>

// ---------------------------------------------------------------------------
// EncoderLayer: x -> MHA(flash) -> add&LN -> FF(relu) -> add&LN
// B=4, S=2048, D=1024, H=16, hd=64, FF=4096, fp32 in/out.
// Round 5: 3-stage BK=16 GEMM (2 CTAs/SM, depth-2 pipeline intact),
// flash with BKV=32 smem-P (2 CTAs/SM, no spills), merged QKV launch.
// ---------------------------------------------------------------------------

namespace cfg {
constexpr int D_MODEL = 1024;
constexpr int NHEADS  = 16;
constexpr int HDIM    = 64;
constexpr int DFF     = 4096;
constexpr int BATCH   = 4;
constexpr int SEQ     = 2048;
constexpr int NTOK    = BATCH * SEQ;   // 8192
}

// ------------------------------ scratch ------------------------------------
__device__ float g_q   [(size_t)cfg::NTOK * cfg::D_MODEL];
__device__ float g_k   [(size_t)cfg::NTOK * cfg::D_MODEL];
__device__ float g_v   [(size_t)cfg::NTOK * cfg::D_MODEL];
__device__ float g_attn[(size_t)cfg::NTOK * cfg::D_MODEL];
__device__ float g_h   [(size_t)cfg::NTOK * cfg::D_MODEL];
__device__ float g_ff  [(size_t)cfg::NTOK * cfg::DFF];

// ------------------------------ helpers ------------------------------------
__device__ __forceinline__ void cp16(void* s, const void* g) {
    uint32_t sa = (uint32_t)__cvta_generic_to_shared(s);
    asm volatile("cp.async.cg.shared.global [%0], [%1], 16;\n" :: "r"(sa), "l"(g));
}
__device__ __forceinline__ void cp_commit() {
    asm volatile("cp.async.commit_group;\n");
}
template <int N>
__device__ __forceinline__ void cp_wait() {
    asm volatile("cp.async.wait_group %0;\n" :: "n"(N));
}

// mma with raw fp32 operands interpreted as tf32 (RZ truncation in HW).
__device__ __forceinline__ void mma_m16n8k8(float* c, const uint32_t* a, const uint32_t* b) {
    asm volatile(
        "mma.sync.aligned.m16n8k8.row.col.f32.tf32.tf32.f32 "
        "{%0,%1,%2,%3}, {%4,%5,%6,%7}, {%8,%9}, {%0,%1,%2,%3};\n"
        : "+f"(c[0]), "+f"(c[1]), "+f"(c[2]), "+f"(c[3])
        : "r"(a[0]), "r"(a[1]), "r"(a[2]), "r"(a[3]),
          "r"(b[0]), "r"(b[1]));
}

// ------------------------------ GEMM (cp.async, 3-stage, BK=16) -------------
// C[M,N] = alpha * A[M,K] @ B[K,N] + bias, optional ReLU. Row-major.
namespace gg {
constexpr int BM = 128, BN = 128, BK = 16, STG = 3;
constexpr int LDA = 20;    // (20*grp+tg)%32 all-distinct -> conflict-free
constexpr int LDB = 136;   // (8*tg+grp)%32 all-distinct  -> conflict-free
constexpr int STAGE_FLOATS = BM * LDA + BK * LDB;   // 2560+2176 = 4736
constexpr int SMEM_BYTES = STG * STAGE_FLOATS * 4;  // 56832
}

template <bool RELU>
__device__ __forceinline__ void gemm_body(
    const float* __restrict__ A, const float* __restrict__ B,
    const float* __restrict__ bias, float* __restrict__ C,
    int N, int K, float alpha, float* sm, int bm, int bn)
{
    using namespace gg;
    const int tid  = threadIdx.x;
    const int lane = tid & 31;
    const int warp = tid >> 5;
    const int wm   = warp & 1;          // 2 warps along M (64 each)
    const int wn   = warp >> 1;         // 4 warps along N (32 each)
    const int grp  = lane >> 2;
    const int tg   = lane & 3;

    const int at_row = tid >> 2;            // 0..63, +i*64
    const int at_col = (tid & 3) << 2;      // 0..12
    const int bt_row = tid >> 5;            // 0..7, +i*8
    const int bt_col = (tid & 31) << 2;     // 0..124

    auto issue = [&](int kt, int stg) {
        float* sA = sm + stg * STAGE_FLOATS;
        float* sB = sA + BM * LDA;
        const int k0 = kt * BK;
        #pragma unroll
        for (int i = 0; i < 2; i++) {
            int r = at_row + i * 64;
            cp16(&sA[r * LDA + at_col],
                 &A[(size_t)(bm + r) * K + k0 + at_col]);
        }
        #pragma unroll
        for (int i = 0; i < 2; i++) {
            int r = bt_row + i * 8;
            cp16(&sB[r * LDB + bt_col],
                 &B[(size_t)(k0 + r) * N + bn + bt_col]);
        }
    };

    float acc[4][4][4];
    #pragma unroll
    for (int mi = 0; mi < 4; mi++)
        #pragma unroll
        for (int ni = 0; ni < 4; ni++)
            #pragma unroll
            for (int j = 0; j < 4; j++) acc[mi][ni][j] = 0.f;

    const int ntiles = K / BK;
    issue(0, 0); cp_commit();
    issue(1, 1); cp_commit();

    int stg = 2;   // stage to fill next
    for (int kt = 0; kt < ntiles; kt++) {
        cp_wait<1>();
        __syncthreads();
        if (kt + 2 < ntiles) issue(kt + 2, stg);
        cp_commit();

        // compute stage = (kt % 3)
        const int cs = kt - (kt / 3) * 3;
        const float* sA = sm + cs * STAGE_FLOATS;
        const float* sB = sA + BM * LDA;

        #pragma unroll
        for (int kk = 0; kk < BK; kk += 8) {
            uint32_t af[4][4];
            uint32_t bf[4][2];
            #pragma unroll
            for (int mi = 0; mi < 4; mi++) {
                const int r = wm * 64 + mi * 16;
                af[mi][0] = __float_as_uint(sA[(r + grp    ) * LDA + kk + tg    ]);
                af[mi][1] = __float_as_uint(sA[(r + grp + 8) * LDA + kk + tg    ]);
                af[mi][2] = __float_as_uint(sA[(r + grp    ) * LDA + kk + tg + 4]);
                af[mi][3] = __float_as_uint(sA[(r + grp + 8) * LDA + kk + tg + 4]);
            }
            #pragma unroll
            for (int ni = 0; ni < 4; ni++) {
                const int c = wn * 32 + ni * 8 + grp;
                bf[ni][0] = __float_as_uint(sB[(kk + tg    ) * LDB + c]);
                bf[ni][1] = __float_as_uint(sB[(kk + tg + 4) * LDB + c]);
            }
            #pragma unroll
            for (int mi = 0; mi < 4; mi++)
                #pragma unroll
                for (int ni = 0; ni < 4; ni++)
                    mma_m16n8k8(acc[mi][ni], af[mi], bf[ni]);
        }

        stg = cs;  // the stage just consumed becomes the next fill target
    }

    #pragma unroll
    for (int mi = 0; mi < 4; mi++) {
        const int r0 = bm + wm * 64 + mi * 16 + grp;
        #pragma unroll
        for (int ni = 0; ni < 4; ni++) {
            const int c0 = bn + wn * 32 + ni * 8 + tg * 2;
            float bv0 = 0.f, bv1 = 0.f;
            if (bias) { bv0 = __ldg(&bias[c0]); bv1 = __ldg(&bias[c0 + 1]); }
            float v0 = acc[mi][ni][0] * alpha + bv0;
            float v1 = acc[mi][ni][1] * alpha + bv1;
            float v2 = acc[mi][ni][2] * alpha + bv0;
            float v3 = acc[mi][ni][3] * alpha + bv1;
            if (RELU) {
                v0 = fmaxf(v0, 0.f); v1 = fmaxf(v1, 0.f);
                v2 = fmaxf(v2, 0.f); v3 = fmaxf(v3, 0.f);
            }
            *reinterpret_cast<float2*>(&C[(size_t)r0 * N + c0]) =
                make_float2(v0, v1);
            *reinterpret_cast<float2*>(&C[(size_t)(r0 + 8) * N + c0]) =
                make_float2(v2, v3);
        }
    }
}

template <bool RELU>
__global__ void __launch_bounds__(256, 2) gemm_cp(
    const float* __restrict__ A, const float* __restrict__ B,
    const float* __restrict__ bias, float* __restrict__ C,
    int N, int K, float alpha)
{
    extern __shared__ float sm[];
    gemm_body<RELU>(A, B, bias, C, N, K, alpha, sm,
                    blockIdx.y * gg::BM, blockIdx.x * gg::BN);
}

// Merged QKV: blockIdx.z in {0,1,2} selects (W,b,out).
__global__ void __launch_bounds__(256, 2) gemm_qkv(
    const float* __restrict__ X,
    const float* __restrict__ Wq, const float* __restrict__ bq, float* __restrict__ q,
    const float* __restrict__ Wk, const float* __restrict__ bk, float* __restrict__ k,
    const float* __restrict__ Wv, const float* __restrict__ bv, float* __restrict__ v)
{
    extern __shared__ float sm[];
    const float* W;
    const float* bi;
    float* C;
    if (blockIdx.z == 0)      { W = Wq; bi = bq; C = q; }
    else if (blockIdx.z == 1) { W = Wk; bi = bk; C = k; }
    else                      { W = Wv; bi = bv; C = v; }
    gemm_body<false>(X, W, bi, C, cfg::D_MODEL, cfg::D_MODEL, 1.f, sm,
                     blockIdx.y * gg::BM, blockIdx.x * gg::BN);
}

// --------------------------- flash attention --------------------------------
// One CTA = 128 Q rows of one (b,h). 8 warps x 16 rows. KV chunks of 32,
// double-buffered via cp.async. P staged through smem (warp-private rows).
// 2 CTAs/SM (regs ~110 < 128, smem 70.7KB).
namespace fa {
constexpr int BQ  = 128;
constexpr int BKV = 32;
constexpr int LDK = 68;
constexpr int LDV = 72;
constexpr int LDP = 68;
constexpr int SMEM_FLOATS = 2 * BKV * LDK + 2 * BKV * LDV + BQ * LDP; // 17664
constexpr int SMEM_BYTES  = SMEM_FLOATS * 4;                          // 70656
}

__global__ void __launch_bounds__(256, 2) flash_attn(
    const float* __restrict__ Q, const float* __restrict__ K,
    const float* __restrict__ V, float* __restrict__ O)
{
    using namespace fa;
    extern __shared__ float sm[];
    float* Ks = sm;
    float* Vs = sm + 2 * BKV * LDK;
    float* Ps = sm + 2 * BKV * LDK + 2 * BKV * LDV;

    const int tid  = threadIdx.x;
    const int lane = tid & 31;
    const int warp = tid >> 5;
    const int grp  = lane >> 2;
    const int tg   = lane & 3;
    const int bh   = blockIdx.y;
    const int b    = bh >> 4;
    const int h    = bh & 15;
    const long long base = (long long)b * ((long long)cfg::SEQ * cfg::D_MODEL)
                         + (long long)h * cfg::HDIM;
    const float* Qp = Q + base;
    const float* Kp = K + base;
    const float* Vp = V + base;
    const int bm   = blockIdx.x * BQ;
    const int wrow = warp * 16;

    const int kr = tid >> 4;           // 0..15
    const int kc = (tid & 15) << 2;    // 0..60

    // ---- stage Q tile (x 1/8) through Ps, read persistent fragments ----
    {
        #pragma unroll
        for (int i = 0; i < 8; i++) {
            int row = kr + i * 16;
            float4 qv = *reinterpret_cast<const float4*>(
                Qp + (long long)(bm + row) * cfg::D_MODEL + kc);
            float* d = &Ps[row * LDP + kc];
            d[0] = qv.x * 0.125f; d[1] = qv.y * 0.125f;
            d[2] = qv.z * 0.125f; d[3] = qv.w * 0.125f;
        }
    }
    __syncthreads();
    uint32_t qf[8][4];
    #pragma unroll
    for (int kk = 0; kk < 8; kk++) {
        qf[kk][0] = __float_as_uint(Ps[(wrow + grp    ) * LDP + kk * 8 + tg    ]);
        qf[kk][1] = __float_as_uint(Ps[(wrow + grp + 8) * LDP + kk * 8 + tg    ]);
        qf[kk][2] = __float_as_uint(Ps[(wrow + grp    ) * LDP + kk * 8 + tg + 4]);
        qf[kk][3] = __float_as_uint(Ps[(wrow + grp + 8) * LDP + kk * 8 + tg + 4]);
    }
    __syncthreads();

    auto issue_kv = [&](int t, int bf) {
        #pragma unroll
        for (int i = 0; i < 2; i++) {
            int row = kr + i * 16;
            long long grow = (long long)(t * BKV + row) * cfg::D_MODEL + kc;
            cp16(&Ks[(bf * BKV + row) * LDK + kc], Kp + grow);
            cp16(&Vs[(bf * BKV + row) * LDV + kc], Vp + grow);
        }
    };

    issue_kv(0, 0); cp_commit();

    float oacc[8][4];
    #pragma unroll
    for (int ni = 0; ni < 8; ni++)
        #pragma unroll
        for (int j = 0; j < 4; j++) oacc[ni][j] = 0.f;
    float m0 = -3.402823466e38f, m1 = -3.402823466e38f;
    float l0 = 0.f, l1 = 0.f;

    constexpr int NT = cfg::SEQ / BKV;   // 64
    for (int t = 0; t < NT; t++) {
        cp_wait<0>();
        __syncthreads();
        if (t + 1 < NT) issue_kv(t + 1, (t + 1) & 1);
        cp_commit();

        const int buf = t & 1;

        // ---- S = (Q/8) @ K^T   (128 x 32) ----
        float sacc[4][4];
        #pragma unroll
        for (int ni = 0; ni < 4; ni++)
            #pragma unroll
            for (int j = 0; j < 4; j++) sacc[ni][j] = 0.f;

        const float* Kb = Ks + buf * BKV * LDK;
        #pragma unroll
        for (int kk = 0; kk < 8; kk++) {
            #pragma unroll
            for (int ni = 0; ni < 4; ni++) {
                uint32_t bb[2] = {
                    __float_as_uint(Kb[(ni * 8 + grp) * LDK + kk * 8 + tg    ]),
                    __float_as_uint(Kb[(ni * 8 + grp) * LDK + kk * 8 + tg + 4])};
                mma_m16n8k8(sacc[ni], qf[kk], bb);
            }
        }

        // ---- online softmax (rows grp and grp+8 of this warp) ----
        float mx0 = fmaxf(fmaxf(sacc[0][0], sacc[0][1]), fmaxf(sacc[1][0], sacc[1][1]));
        float mx1 = fmaxf(fmaxf(sacc[0][2], sacc[0][3]), fmaxf(sacc[1][2], sacc[1][3]));
        mx0 = fmaxf(mx0, fmaxf(fmaxf(sacc[2][0], sacc[2][1]), fmaxf(sacc[3][0], sacc[3][1])));
        mx1 = fmaxf(mx1, fmaxf(fmaxf(sacc[2][2], sacc[2][3]), fmaxf(sacc[3][2], sacc[3][3])));
        mx0 = fmaxf(mx0, __shfl_xor_sync(0xffffffffu, mx0, 1));
        mx0 = fmaxf(mx0, __shfl_xor_sync(0xffffffffu, mx0, 2));
        mx1 = fmaxf(mx1, __shfl_xor_sync(0xffffffffu, mx1, 1));
        mx1 = fmaxf(mx1, __shfl_xor_sync(0xffffffffu, mx1, 2));

        const float mn0 = fmaxf(m0, mx0);
        const float mn1 = fmaxf(m1, mx1);
        const float a0  = __expf(m0 - mn0);
        const float a1  = __expf(m1 - mn1);
        m0 = mn0; m1 = mn1;

        float rs0 = 0.f, rs1 = 0.f;
        #pragma unroll
        for (int ni = 0; ni < 4; ni++) {
            float p0 = __expf(sacc[ni][0] - m0);
            float p1 = __expf(sacc[ni][1] - m0);
            float p2 = __expf(sacc[ni][2] - m1);
            float p3 = __expf(sacc[ni][3] - m1);
            rs0 += p0 + p1;
            rs1 += p2 + p3;
            const int c = ni * 8 + tg * 2;
            float* w0 = &Ps[(wrow + grp) * LDP + c];
            w0[0] = p0; w0[1] = p1;
            float* w1 = &Ps[(wrow + grp + 8) * LDP + c];
            w1[0] = p2; w1[1] = p3;
        }
        l0 = l0 * a0 + rs0;
        l1 = l1 * a1 + rs1;
        #pragma unroll
        for (int ni = 0; ni < 8; ni++) {
            oacc[ni][0] *= a0; oacc[ni][1] *= a0;
            oacc[ni][2] *= a1; oacc[ni][3] *= a1;
        }
        __syncwarp();

        // ---- O += P @ V   (k = 32) ----
        const float* Vb = Vs + buf * BKV * LDV;
        #pragma unroll
        for (int kk = 0; kk < 4; kk++) {
            uint32_t af[4];
            af[0] = __float_as_uint(Ps[(wrow + grp    ) * LDP + kk * 8 + tg    ]);
            af[1] = __float_as_uint(Ps[(wrow + grp + 8) * LDP + kk * 8 + tg    ]);
            af[2] = __float_as_uint(Ps[(wrow + grp    ) * LDP + kk * 8 + tg + 4]);
            af[3] = __float_as_uint(Ps[(wrow + grp + 8) * LDP + kk * 8 + tg + 4]);
            #pragma unroll
            for (int ni = 0; ni < 8; ni++) {
                uint32_t bb[2] = {
                    __float_as_uint(Vb[(kk * 8 + tg    ) * LDV + ni * 8 + grp]),
                    __float_as_uint(Vb[(kk * 8 + tg + 4) * LDV + ni * 8 + grp])};
                mma_m16n8k8(oacc[ni], af, bb);
            }
        }
        __syncwarp();
    }

    // ---- epilogue: normalize and store ----
    l0 += __shfl_xor_sync(0xffffffffu, l0, 1);
    l0 += __shfl_xor_sync(0xffffffffu, l0, 2);
    l1 += __shfl_xor_sync(0xffffffffu, l1, 1);
    l1 += __shfl_xor_sync(0xffffffffu, l1, 2);
    const float inv0 = 1.f / l0;
    const float inv1 = 1.f / l1;

    const long long tok0 = (long long)b * cfg::SEQ + bm + wrow + grp;
    #pragma unroll
    for (int ni = 0; ni < 8; ni++) {
        const int c = h * cfg::HDIM + ni * 8 + tg * 2;
        *reinterpret_cast<float2*>(&O[tok0 * cfg::D_MODEL + c]) =
            make_float2(oacc[ni][0] * inv0, oacc[ni][1] * inv0);
        *reinterpret_cast<float2*>(&O[(tok0 + 8) * cfg::D_MODEL + c]) =
            make_float2(oacc[ni][2] * inv1, oacc[ni][3] * inv1);
    }
}

// ------------------------------ add + LayerNorm ----------------------------
__global__ void __launch_bounds__(256) add_ln_kernel(
    const float* __restrict__ a, const float* __restrict__ b,
    const float* __restrict__ gamma, const float* __restrict__ beta,
    float* __restrict__ outp)
{
    const long long row = blockIdx.x;
    const float* pa = a + row * cfg::D_MODEL;
    const float* pb = b + row * cfg::D_MODEL;
    float* po = outp + row * cfg::D_MODEL;
    const int tid = threadIdx.x;

    float v[4];
    float s = 0.f, sq = 0.f;
    #pragma unroll
    for (int i = 0; i < 4; i++) {
        const int c = i * 256 + tid;
        v[i] = pa[c] + pb[c];
        s += v[i];
        sq += v[i] * v[i];
    }

    __shared__ float r1[8], r2[8];
    #pragma unroll
    for (int o = 16; o > 0; o >>= 1) {
        s  += __shfl_xor_sync(0xffffffffu, s, o);
        sq += __shfl_xor_sync(0xffffffffu, sq, o);
    }
    if ((tid & 31) == 0) { r1[tid >> 5] = s; r2[tid >> 5] = sq; }
    __syncthreads();
    s = 0.f; sq = 0.f;
    #pragma unroll
    for (int j = 0; j < 8; j++) { s += r1[j]; sq += r2[j]; }

    const float mu   = s * (1.f / cfg::D_MODEL);
    const float var  = sq * (1.f / cfg::D_MODEL) - mu * mu;
    const float rstd = rsqrtf(var + 1e-5f);

    #pragma unroll
    for (int i = 0; i < 4; i++) {
        const int c = i * 256 + tid;
        po[c] = (v[i] - mu) * rstd * __ldg(&gamma[c]) + __ldg(&beta[c]);
    }
}

// ------------------------------ launch -------------------------------------
extern "C" void kernel_launch(void* const* d_in, const int* in_sizes, int n_in,
                              void* d_out, int out_size)
{
    using namespace cfg;
    const float* x   = (const float*)d_in[0];
    const float* Wq  = (const float*)d_in[1];
    const float* bq  = (const float*)d_in[2];
    const float* Wk  = (const float*)d_in[3];
    const float* bk_ = (const float*)d_in[4];
    const float* Wv  = (const float*)d_in[5];
    const float* bv  = (const float*)d_in[6];
    const float* Wo  = (const float*)d_in[7];
    const float* bo  = (const float*)d_in[8];
    const float* W1  = (const float*)d_in[9];
    const float* b1  = (const float*)d_in[10];
    const float* W2  = (const float*)d_in[11];
    const float* b2  = (const float*)d_in[12];
    const float* g1  = (const float*)d_in[13];
    const float* be1 = (const float*)d_in[14];
    const float* g2  = (const float*)d_in[15];
    const float* be2 = (const float*)d_in[16];
    float* out = (float*)d_out;

    float *q, *k, *v, *attn, *h, *ff;
    cudaGetSymbolAddress((void**)&q,    g_q);
    cudaGetSymbolAddress((void**)&k,    g_k);
    cudaGetSymbolAddress((void**)&v,    g_v);
    cudaGetSymbolAddress((void**)&attn, g_attn);
    cudaGetSymbolAddress((void**)&h,    g_h);
    cudaGetSymbolAddress((void**)&ff,   g_ff);

    static bool attr_done = false;
    if (!attr_done) {
        cudaFuncSetAttribute(flash_attn,
                             cudaFuncAttributeMaxDynamicSharedMemorySize,
                             fa::SMEM_BYTES);
        cudaFuncSetAttribute(gemm_cp<false>,
                             cudaFuncAttributeMaxDynamicSharedMemorySize,
                             gg::SMEM_BYTES);
        cudaFuncSetAttribute(gemm_cp<true>,
                             cudaFuncAttributeMaxDynamicSharedMemorySize,
                             gg::SMEM_BYTES);
        cudaFuncSetAttribute(gemm_qkv,
                             cudaFuncAttributeMaxDynamicSharedMemorySize,
                             gg::SMEM_BYTES);
        attr_done = true;
    }

    // 1) Q/K/V projections (merged: z selects weight set)
    {
        dim3 grid(D_MODEL / 128, NTOK / 128, 3);
        gemm_qkv<<<grid, 256, gg::SMEM_BYTES>>>(
            x, Wq, bq, q, Wk, bk_, k, Wv, bv, v);
    }

    // 2-4) fused flash attention -> attn
    {
        dim3 grid(SEQ / fa::BQ, BATCH * NHEADS);
        flash_attn<<<grid, 256, fa::SMEM_BYTES>>>(q, k, v, attn);
    }

    // 5) output projection: attn @ Wo + bo -> reuse q
    {
        dim3 grid(D_MODEL / 128, NTOK / 128);
        gemm_cp<false><<<grid, 256, gg::SMEM_BYTES>>>(attn, Wo, bo, q, D_MODEL, D_MODEL, 1.f);
    }

    // 6) h = LN(x + proj)
    add_ln_kernel<<<NTOK, 256>>>(x, q, g1, be1, h);

    // 7) ff = relu(h @ W1 + b1)
    {
        dim3 grid(DFF / 128, NTOK / 128);
        gemm_cp<true><<<grid, 256, gg::SMEM_BYTES>>>(h, W1, b1, ff, DFF, D_MODEL, 1.f);
    }

    // 8) ff2 = ff @ W2 + b2 -> reuse k
    {
        dim3 grid(D_MODEL / 128, NTOK / 128);
        gemm_cp<false><<<grid, 256, gg::SMEM_BYTES>>>(ff, W2, b2, k, D_MODEL, DFF, 1.f);
    }

    // 9) out = LN(h + ff2)
    add_ln_kernel<<<NTOK, 256>>>(h, k, g2, be2, out);
}